// round 11
// baseline (speedup 1.0000x reference)
#include <cuda_runtime.h>

#define B_ROWS 8192
#define P_ROWS 1024
#define D_DIM  256
#define NPART  32              // K1 producer blocks; 32 proto rows each
#define G3     512             // K3 blocks
#define T3     256             // K3 threads: 8 warps, 2 rows/warp -> 16 rows/block

// Inter-kernel scratch (allocation-free rule: device globals, zero-init).
__device__ float g_partial[NPART * D_DIM];   // per-block column sums
__device__ float g_p2[NPART];                // per-block sum of squares
__device__ float g_m2[D_DIM];                // FINAL: 2*mean_p proto[:,d]
__device__ float g_c;                        // FINAL: mean_p ||p||^2
__device__ unsigned int g_count = 0;         // k1-internal arrivals (32 total)

// ---------------------------------------------------------------------------
// K1: complete prototype job. 32 blocks; last-arriving block combines partials
// into the FINAL g_m2/g_c, so K3 has zero combine work. Signals dependents
// immediately so K3's x-stream overlaps all of this.
// ---------------------------------------------------------------------------
__global__ void __launch_bounds__(256) k1_proto(const float* __restrict__ proto) {
    asm volatile("griddepcontrol.launch_dependents;");

    const int tid  = threadIdx.x;
    const int lane = tid & 31;
    const int warp = tid >> 5;
    const int c4   = tid & 63;               // float4 column group
    const int g    = tid >> 6;               // 4 row-groups of 8 rows
    const int row0 = blockIdx.x * (P_ROWS / NPART) + g * 8;

    __shared__ __align__(16) float sg[4 * D_DIM];
    __shared__ float sp[8];
    __shared__ unsigned int sm_role;

    float4 s = make_float4(0.f, 0.f, 0.f, 0.f);
    float sq = 0.f;
#pragma unroll
    for (int r = 0; r < 8; ++r) {            // 8 independent float4 loads
        float4 v = *reinterpret_cast<const float4*>(
            proto + (row0 + r) * D_DIM + c4 * 4);
        s.x += v.x; s.y += v.y; s.z += v.z; s.w += v.w;
        sq  += v.x * v.x + v.y * v.y + v.z * v.z + v.w * v.w;
    }
    *reinterpret_cast<float4*>(&sg[g * D_DIM + c4 * 4]) = s;

#pragma unroll
    for (int o = 16; o > 0; o >>= 1)
        sq += __shfl_down_sync(0xFFFFFFFFu, sq, o);
    if (lane == 0) sp[warp] = sq;
    __syncthreads();

    g_partial[blockIdx.x * D_DIM + tid] =
        sg[tid] + sg[D_DIM + tid] + sg[2 * D_DIM + tid] + sg[3 * D_DIM + tid];
    if (tid == 0) {
        float p2 = 0.f;
#pragma unroll
        for (int i = 0; i < 8; ++i) p2 += sp[i];
        g_p2[blockIdx.x] = p2;
    }

    // every thread fences its own stores; one arrival per block
    __threadfence();
    __syncthreads();
    if (tid == 0) {
        unsigned int old = atomicAdd(&g_count, 1u);
        sm_role = (old == NPART - 1) ? 1u : 0u;
    }
    __syncthreads();

    // ---- last-arriving block: combine 32 partials -> FINAL m2/c --------------
    if (sm_role) {
        __threadfence();                     // acquire: order reads after atomic
        float s2 = 0.f;
#pragma unroll
        for (int i = 0; i < NPART; ++i)      // 32 L2-hit loads, MLP=32
            s2 += __ldcg(&g_partial[i * D_DIM + tid]);
        g_m2[tid] = s2 * (2.0f / (float)P_ROWS);

        if (warp == 0) {                     // 32 lanes <-> 32 p2 partials
            float v = __ldcg(&g_p2[lane]);
#pragma unroll
            for (int o = 16; o > 0; o >>= 1)
                v += __shfl_down_sync(0xFFFFFFFFu, v, o);
            if (lane == 0) g_c = v * (1.0f / (float)P_ROWS);
        }
        if (tid == 0) g_count = 0;           // reset for next graph replay
        // kernel-completion boundary publishes everything to K3 (PDL wait)
    }
}

// ---------------------------------------------------------------------------
// K3: minimal consumer. 512 blocks x 256 thr, 2 rows/warp.
// x loads issue BEFORE the PDL wait (pure input); after the wait: 3 L2 loads,
// 16 FMAs, shuffle reduce, store. No combine, no barriers, no smem.
// Lane L covers d in [4L,4L+4) and [128+4L,128+4L+4): each LDG.128 is a fully
// coalesced 512B warp transaction (4 cache lines).
// ---------------------------------------------------------------------------
__global__ void __launch_bounds__(T3) k3_main(const float* __restrict__ x,
                                             float* __restrict__ out) {
    const int tid  = threadIdx.x;
    const int lane = tid & 31;
    const int warp = tid >> 5;
    const int row0 = blockIdx.x * 16 + warp * 2;

    const float* r0 = x + row0 * D_DIM + lane * 4;
    const float* r1 = r0 + D_DIM;

    float4 a0 = *reinterpret_cast<const float4*>(r0);            // d: 4L..
    float4 a1 = *reinterpret_cast<const float4*>(r0 + 128);      // d: 128+4L..
    float4 b0 = *reinterpret_cast<const float4*>(r1);
    float4 b1 = *reinterpret_cast<const float4*>(r1 + 128);

    asm volatile("griddepcontrol.wait;" ::: "memory");           // K1 done

    const float4 m0 = __ldcg(reinterpret_cast<const float4*>(&g_m2[lane * 4]));
    const float4 m1 = __ldcg(reinterpret_cast<const float4*>(&g_m2[128 + lane * 4]));
    const float  c  = __ldcg(&g_c);

    float acc0, acc1;
    acc0  = a0.x * (a0.x - m0.x);  acc1  = b0.x * (b0.x - m0.x);
    acc0 += a0.y * (a0.y - m0.y);  acc1 += b0.y * (b0.y - m0.y);
    acc0 += a0.z * (a0.z - m0.z);  acc1 += b0.z * (b0.z - m0.z);
    acc0 += a0.w * (a0.w - m0.w);  acc1 += b0.w * (b0.w - m0.w);
    acc0 += a1.x * (a1.x - m1.x);  acc1 += b1.x * (b1.x - m1.x);
    acc0 += a1.y * (a1.y - m1.y);  acc1 += b1.y * (b1.y - m1.y);
    acc0 += a1.z * (a1.z - m1.z);  acc1 += b1.z * (b1.z - m1.z);
    acc0 += a1.w * (a1.w - m1.w);  acc1 += b1.w * (b1.w - m1.w);

#pragma unroll
    for (int o = 16; o > 0; o >>= 1) {
        acc0 += __shfl_down_sync(0xFFFFFFFFu, acc0, o);
        acc1 += __shfl_down_sync(0xFFFFFFFFu, acc1, o);
    }
    if (lane == 0) {
        out[row0]     = acc0 + c;
        out[row0 + 1] = acc1 + c;
    }
}

extern "C" void kernel_launch(void* const* d_in, const int* in_sizes, int n_in,
                              void* d_out, int out_size) {
    const float* x     = (const float*)d_in[0];  // (8192, 256) float32
    const float* proto = (const float*)d_in[1];  // (1024, 256) float32
    float* out = (float*)d_out;                  // (8192,) float32

    k1_proto<<<NPART, 256>>>(proto);

    // K3 with programmatic dependent launch: overlaps K1; degrades to normal
    // stream order (still correct) if PDL is unavailable.
    cudaLaunchConfig_t cfg = {};
    cfg.gridDim  = dim3(G3, 1, 1);
    cfg.blockDim = dim3(T3, 1, 1);
    cfg.dynamicSmemBytes = 0;
    cudaLaunchAttribute attr[1];
    attr[0].id = cudaLaunchAttributeProgrammaticStreamSerialization;
    attr[0].val.programmaticStreamSerializationAllowed = 1;
    cfg.attrs    = attr;
    cfg.numAttrs = 1;
    cudaLaunchKernelEx(&cfg, k3_main, x, out);
}